// round 13
// baseline (speedup 1.0000x reference)
#include <cuda_runtime.h>
#include <cuda_bf16.h>

#define N_NODE 1025
#define F3     96
#define KCONV  36864
#define KLIN   4096
#define OUT_OC 0
#define OUT_OL 18874368
#define OUT_OB 19922944

// ---------------- scratch ----------------------------------------------------
__device__ float g_encG[32 * KCONV];   // conv enc weights gathered, [h][K]
__device__ float g_linG[32 * KLIN];    // lin  enc weights gathered, [h][K]
__device__ float g_feats[N_NODE * F3];
__device__ float g_dinv[N_NODE];
__device__ float g_t1[N_NODE * F3];
__device__ float g_h[N_NODE * F3];
__device__ float g_t2[N_NODE * F3];
__device__ float g_x[N_NODE * F3];

__device__ __forceinline__ int conv_idx(int t) {
    int r = t / 9, s = t - r * 9;
    int a = r >> 6, b = r & 63;
    return a * 1152 + b * 9 + s;
}
__device__ __forceinline__ int lin_idx(int t) {
    return ((t >> 6) << 7) + (t & 63);
}

__device__ __forceinline__ void mma_tf32(float c[4], const unsigned a[4], const unsigned b[2]) {
    asm volatile("mma.sync.aligned.m16n8k8.row.col.f32.tf32.tf32.f32 "
                 "{%0,%1,%2,%3}, {%4,%5,%6,%7}, {%8,%9}, {%0,%1,%2,%3};"
                 : "+f"(c[0]), "+f"(c[1]), "+f"(c[2]), "+f"(c[3])
                 : "r"(a[0]), "r"(a[1]), "r"(a[2]), "r"(a[3]),
                   "r"(b[0]), "r"(b[1]));
}

__device__ __forceinline__ void cp16(unsigned dst_smem, const void* src) {
    asm volatile("cp.async.cg.shared.global [%0], [%1], 16;" :: "r"(dst_smem), "l"(src));
}

// ---------------- 1. gather BOTH encoder weight sets (one launch) -----------
__global__ void k_prep_both(const float* __restrict__ Wc, const float* __restrict__ Wl) {
    int h = blockIdx.y;
    if (blockIdx.x < 144) {
        int t = blockIdx.x * 256 + threadIdx.x;
        g_encG[h * KCONV + t] = Wc[h * 147456 + conv_idx(t)];
    } else {
        int t = (blockIdx.x - 144) * 256 + threadIdx.x;
        g_linG[h * KLIN + t] = Wl[h * 16384 + lin_idx(t)];
    }
}

// ---------------- 2. init feats + dinv (fused) ------------------------------
__global__ void k_init_dinv(const float* __restrict__ ceb, const float* __restrict__ leb,
                            const float* __restrict__ emb, const int* __restrict__ prims,
                            const int* __restrict__ adj) {
    int i = blockIdx.x;

    int e = i * 256 + threadIdx.x;
    if (e < N_NODE * F3) {
        int row = e / F3, c = e - row * F3;
        float v;
        if (row == 0) v = 1.0f;
        else {
            int ii = row - 1;
            if (c >= 64)      v = emb[prims[ii] * 32 + (c - 64)];
            else {
                int h = c & 31;
                if (ii < 512)      v = ceb[h];
                else if (ii < 768) v = leb[h];
                else               v = 0.0f;
            }
        }
        g_feats[e] = v;
    }

    __shared__ int red[256];
    int s = 0;
    for (int j = threadIdx.x; j < N_NODE; j += 256) s += adj[i * N_NODE + j];
    red[threadIdx.x] = s;
    __syncthreads();
    for (int off = 128; off > 0; off >>= 1) {
        if (threadIdx.x < off) red[threadIdx.x] += red[threadIdx.x + off];
        __syncthreads();
    }
    if (threadIdx.x == 0) g_dinv[i] = rsqrtf((float)(red[0] + 1));
}

// ---------------- 4. encoder GEMM, tf32 + cp.async (conv+lin in one) --------
// blockIdx.y < 72: conv block (x=rowtile, y=ksplit of 512)
// blockIdx.y >= 72: lin block id = (y-72)*8 + x  ->  rowtile id&3, ksplit id>>2
__global__ __launch_bounds__(256) void k_enc_tf32(const float* __restrict__ Ac,
                                                  const float* __restrict__ Al) {
    __shared__ unsigned As[3][64 * 40];
    __shared__ unsigned Bs[3][32 * 40];

    const float* A;
    const float* B;
    int K, featrow0, rowb, kbase;
    if (blockIdx.y < 72) {
        A = Ac; B = g_encG; K = KCONV; featrow0 = 1;
        rowb = blockIdx.x * 64;
        kbase = blockIdx.y * 512;
    } else {
        A = Al; B = g_linG; K = KLIN; featrow0 = 513;
        int id = (blockIdx.y - 72) * 8 + blockIdx.x;
        rowb = (id & 3) * 64;
        kbase = (id >> 2) * 512;
    }

    int tid = threadIdx.x;
    int warp = tid >> 5, lane = tid & 31;
    int g = lane >> 2, tg = lane & 3;
    int wm0 = (warp >> 1) * 16;
    int wn0 = (warp & 1) * 16;

    int mA0 = tid >> 3,            kqA0 = tid & 7;
    int mA1 = (tid + 256) >> 3,    kqA1 = (tid + 256) & 7;
    int mB  = tid >> 3,            kqB  = tid & 7;

    unsigned sA0[3], sA1[3], sB[3];
#pragma unroll
    for (int b = 0; b < 3; b++) {
        sA0[b] = (unsigned)__cvta_generic_to_shared(&As[b][mA0 * 40 + kqA0 * 4]);
        sA1[b] = (unsigned)__cvta_generic_to_shared(&As[b][mA1 * 40 + kqA1 * 4]);
        sB[b]  = (unsigned)__cvta_generic_to_shared(&Bs[b][mB * 40 + kqB * 4]);
    }

    const int NC = 16;
    auto issue = [&](int c) {
        int k0 = kbase + c * 32;
        int buf = c % 3;
        cp16(sA0[buf], &A[(rowb + mA0) * K + k0 + kqA0 * 4]);
        cp16(sA1[buf], &A[(rowb + mA1) * K + k0 + kqA1 * 4]);
        cp16(sB[buf],  &B[mB * K + k0 + kqB * 4]);
        asm volatile("cp.async.commit_group;");
    };

    issue(0);
    issue(1);

    float acc[2][4] = {};

    for (int c = 0; c < NC; c++) {
        if (c + 2 < NC) {
            issue(c + 2);
            asm volatile("cp.async.wait_group 2;");
        } else if (c + 1 < NC) {
            asm volatile("cp.async.wait_group 1;");
        } else {
            asm volatile("cp.async.wait_group 0;");
        }
        __syncthreads();

        const unsigned* Ab = As[c % 3];
        const unsigned* Bb = Bs[c % 3];
#pragma unroll
        for (int ks = 0; ks < 4; ks++) {
            int kk = ks * 8;
            unsigned a[4], b[2][2];
            a[0] = Ab[(wm0 + g) * 40 + kk + tg];
            a[1] = Ab[(wm0 + g + 8) * 40 + kk + tg];
            a[2] = Ab[(wm0 + g) * 40 + kk + tg + 4];
            a[3] = Ab[(wm0 + g + 8) * 40 + kk + tg + 4];
#pragma unroll
            for (int nt = 0; nt < 2; nt++) {
                b[nt][0] = Bb[(wn0 + nt * 8 + g) * 40 + kk + tg];
                b[nt][1] = Bb[(wn0 + nt * 8 + g) * 40 + kk + tg + 4];
            }
#pragma unroll
            for (int nt = 0; nt < 2; nt++) mma_tf32(acc[nt], a, b[nt]);
        }
        __syncthreads();
    }

#pragma unroll
    for (int nt = 0; nt < 2; nt++) {
        int h = wn0 + nt * 8 + 2 * tg;
        int r0 = featrow0 + rowb + wm0 + g;
        atomicAdd(&g_feats[r0 * F3 + h],          acc[nt][0]);
        atomicAdd(&g_feats[r0 * F3 + h + 1],      acc[nt][1]);
        atomicAdd(&g_feats[r0 * F3 + 32 + h],     acc[nt][0]);
        atomicAdd(&g_feats[r0 * F3 + 32 + h + 1], acc[nt][1]);
        int r1 = r0 + 8;
        atomicAdd(&g_feats[r1 * F3 + h],          acc[nt][2]);
        atomicAdd(&g_feats[r1 * F3 + h + 1],      acc[nt][3]);
        atomicAdd(&g_feats[r1 * F3 + 32 + h],     acc[nt][2]);
        atomicAdd(&g_feats[r1 * F3 + 32 + h + 1], acc[nt][3]);
    }
}

// ---------------- 5. bias encoder -------------------------------------------
__global__ void k_bias_enc(const float* __restrict__ bw, const float* __restrict__ Wb,
                           const float* __restrict__ bb) {
    __shared__ float sW[32 * 65];
    __shared__ float sB[8 * 64];
    int tid = threadIdx.x;
    for (int e = tid; e < 32 * 64; e += 256) {
        int hh = e >> 6, t = e & 63;
        sW[hh * 65 + t] = Wb[hh * 128 + t];
    }
    int ibase = blockIdx.x * 8;
    for (int e = tid; e < 8 * 64; e += 256) sB[e] = bw[ibase * 64 + e];
    __syncthreads();
    int h = tid & 31, ii = tid >> 5;
    float acc = 0.0f;
#pragma unroll
    for (int t = 0; t < 64; t++) acc += sB[ii * 64 + t] * sW[h * 65 + t];
    acc += bb[h];
    int row = 769 + ibase + ii;
    g_feats[row * F3 + h] = acc;
    g_feats[row * F3 + 32 + h] = acc;
}

// ---------------- 6. GCN dense GEMM (384 threads, 32 rows/block) ------------
__global__ __launch_bounds__(384) void k_gcn_mm(const float* __restrict__ W, int sel) {
    __shared__ float ws[96 * 96];
    __shared__ float fr[32 * 96];
    const float* __restrict__ in = sel ? g_h : g_feats;
    float* __restrict__ out = sel ? g_t2 : g_t1;
    int tid = threadIdx.x;
    int j = tid % 96, q = tid / 96;
    for (int e = tid; e < 96 * 96; e += 384) ws[e] = W[e];
    int rb = blockIdx.x * 32;
    for (int e = tid; e < 32 * 96; e += 384) {
        int rr = e / 96, c = e - rr * 96;
        int row = rb + rr;
        fr[e] = (row < N_NODE) ? in[row * 96 + c] : 0.0f;
    }
    __syncthreads();
#pragma unroll
    for (int rr8 = 0; rr8 < 8; rr8++) {
        int rr = q * 8 + rr8;
        int row = rb + rr;
        if (row < N_NODE) {
            float acc = 0.0f;
#pragma unroll 8
            for (int k = 0; k < 96; k++) acc += fr[rr * 96 + k] * ws[k * 96 + j];
            out[row * 96 + j] = g_dinv[row] * acc;
        }
    }
}

// ---------------- 7. SpMM ----------------------------------------------------
__global__ void k_spmm(const int* __restrict__ adj, int sel) {
    __shared__ float sT[64 * 96];
    __shared__ float sA[8 * 64];
    const float* __restrict__ ts = sel ? g_t2 : g_t1;
    float* __restrict__ out = sel ? g_x : g_h;
    int j = threadIdx.x, ry = threadIdx.y;
    int tid = ry * 96 + j;
    int rb = blockIdx.x * 8;
    float acc0 = 0.0f, acc1 = 0.0f;
    for (int lb = 0; lb < N_NODE; lb += 64) {
        for (int e = tid; e < 64 * 96; e += 384) {
            int l = e / 96, c = e - l * 96;
            int lg = lb + l;
            sT[e] = (lg < N_NODE) ? ts[lg * 96 + c] : 0.0f;
        }
        for (int e = tid; e < 8 * 64; e += 384) {
            int r = e >> 6, l = e & 63;
            int rg = rb + r, lg = lb + l;
            sA[e] = (rg < N_NODE && lg < N_NODE) ? (float)adj[rg * N_NODE + lg] : 0.0f;
        }
        __syncthreads();
#pragma unroll
        for (int l = 0; l < 64; l += 4) {
            float4 a0 = *(const float4*)&sA[ry * 64 + l];
            float4 a1 = *(const float4*)&sA[(ry + 4) * 64 + l];
            float t0 = sT[(l + 0) * 96 + j], t1 = sT[(l + 1) * 96 + j];
            float t2 = sT[(l + 2) * 96 + j], t3 = sT[(l + 3) * 96 + j];
            acc0 += a0.x * t0 + a0.y * t1 + a0.z * t2 + a0.w * t3;
            acc1 += a1.x * t0 + a1.y * t1 + a1.z * t2 + a1.w * t3;
        }
        __syncthreads();
    }
    int r0 = rb + ry, r1 = rb + ry + 4;
    if (r0 < N_NODE) {
        float v = (acc0 + ts[r0 * 96 + j]) * g_dinv[r0];
        if (!sel) v = fmaxf(v, 0.0f);
        out[r0 * 96 + j] = v;
    }
    if (r1 < N_NODE) {
        float v = (acc1 + ts[r1 * 96 + j]) * g_dinv[r1];
        if (!sel) v = fmaxf(v, 0.0f);
        out[r1 * 96 + j] = v;
    }
}

// ---------------- 8. decoder GEMM: 128M x (jt*64)N, cp.async W --------------
__global__ __launch_bounds__(256) void k_dec_tf32(const float* __restrict__ Wd,
                                                  const float* __restrict__ bd,
                                                  float* __restrict__ out,
                                                  int Ntot, int xrow0, int mode,
                                                  long long outoff, int jt) {
    extern __shared__ unsigned smem[];
    unsigned* Xs = smem;                      // [128][104]
    unsigned* Ws0 = smem + 128 * 104;         // [2][64][104]

    int tid = threadIdx.x;
    int warp = tid >> 5, lane = tid & 31;
    int g = lane >> 2, tg = lane & 3;
    int wm0 = (warp >> 1) * 32;
    int wn0 = (warp & 1) * 32;
    int nbase = blockIdx.x * (jt * 64);
    int ibase = blockIdx.y * 128;

    int wrow[6], wk4[6];
    unsigned wdst[2][6];
#pragma unroll
    for (int i = 0; i < 6; i++) {
        int e = tid + i * 256;
        wrow[i] = e / 24;
        wk4[i] = e - wrow[i] * 24;
        wdst[0][i] = (unsigned)__cvta_generic_to_shared(&Ws0[wrow[i] * 104 + wk4[i] * 4]);
        wdst[1][i] = (unsigned)__cvta_generic_to_shared(&Ws0[64 * 104 + wrow[i] * 104 + wk4[i] * 4]);
    }
    auto issue_w = [&](int j) {
        int buf = j & 1;
#pragma unroll
        for (int i = 0; i < 6; i++) {
            int tglob = nbase + j * 64 + wrow[i];
            int id = (mode == 0) ? conv_idx(tglob) : lin_idx(tglob);
            cp16(wdst[buf][i], &Wd[id * 96 + wk4[i] * 4]);
        }
        asm volatile("cp.async.commit_group;");
    };

    issue_w(0);

#pragma unroll
    for (int i = 0; i < 12; i++) {
        int e = tid + i * 256;
        int m = e / 24, k4 = e - m * 24;
        float4 v = *(const float4*)&g_x[(xrow0 + ibase + m) * 96 + k4 * 4];
        *(float4*)&Xs[m * 104 + k4 * 4] = *(float4*)&v;
    }

    for (int j = 0; j < jt; j++) {
        if (j + 1 < jt) {
            issue_w(j + 1);
            asm volatile("cp.async.wait_group 1;");
        } else {
            asm volatile("cp.async.wait_group 0;");
        }
        __syncthreads();

        int tb = nbase + j * 64;
        float bx[4], by[4];
#pragma unroll
        for (int ni = 0; ni < 4; ni++) {
            int ncol = wn0 + ni * 8 + 2 * tg;
            int t0 = tb + ncol;
            int i0 = (mode == 0) ? conv_idx(t0) : lin_idx(t0);
            int i1 = (mode == 0) ? conv_idx(t0 + 1) : lin_idx(t0 + 1);
            bx[ni] = bd[i0];
            by[ni] = bd[i1];
        }

        const unsigned* Wb = Ws0 + (j & 1) * (64 * 104);
        float acc[2][4][4] = {};
#pragma unroll
        for (int ks = 0; ks < 12; ks++) {
            int k0 = ks * 8;
            unsigned a[2][4], b[4][2];
#pragma unroll
            for (int mi = 0; mi < 2; mi++) {
                int m = wm0 + mi * 16 + g;
                a[mi][0] = Xs[m * 104 + k0 + tg];
                a[mi][1] = Xs[(m + 8) * 104 + k0 + tg];
                a[mi][2] = Xs[m * 104 + k0 + tg + 4];
                a[mi][3] = Xs[(m + 8) * 104 + k0 + tg + 4];
            }
#pragma unroll
            for (int ni = 0; ni < 4; ni++) {
                int n = wn0 + ni * 8 + g;
                b[ni][0] = Wb[n * 104 + k0 + tg];
                b[ni][1] = Wb[n * 104 + k0 + tg + 4];
            }
#pragma unroll
            for (int mi = 0; mi < 2; mi++)
#pragma unroll
                for (int ni = 0; ni < 4; ni++)
                    mma_tf32(acc[mi][ni], a[mi], b[ni]);
        }

#pragma unroll
        for (int mi = 0; mi < 2; mi++) {
            int row0 = ibase + wm0 + mi * 16 + g;
#pragma unroll
            for (int ni = 0; ni < 4; ni++) {
                int col = tb + wn0 + ni * 8 + 2 * tg;
                float2 v0 = make_float2(acc[mi][ni][0] + bx[ni], acc[mi][ni][1] + by[ni]);
                float2 v1 = make_float2(acc[mi][ni][2] + bx[ni], acc[mi][ni][3] + by[ni]);
                *(float2*)&out[outoff + (long long)row0 * Ntot + col] = v0;
                *(float2*)&out[outoff + (long long)(row0 + 8) * Ntot + col] = v1;
            }
        }
        __syncthreads();
    }
}

// ---------------- 9. bias decoder (tiny) ------------------------------------
__global__ void k_dec_bias(const float* __restrict__ Wd, const float* __restrict__ bd,
                           float* __restrict__ out) {
    __shared__ float xr[96];
    int i = blockIdx.x;
    xr[threadIdx.x] = g_x[(769 + i) * 96 + threadIdx.x];
    __syncthreads();
    int t = threadIdx.x;
    if (t < 64) {
        float acc = 0.0f;
#pragma unroll 8
        for (int k = 0; k < 96; k++) acc += xr[k] * Wd[t * 96 + k];
        out[OUT_OB + i * 64 + t] = acc + bd[t];
    }
}

// ---------------- launch -----------------------------------------------------
extern "C" void kernel_launch(void* const* d_in, const int* in_sizes, int n_in,
                              void* d_out, int out_size) {
    const float* conv_w     = (const float*)d_in[0];
    const float* lin_w      = (const float*)d_in[1];
    const float* bias_w     = (const float*)d_in[2];
    const float* conv_enc_w = (const float*)d_in[3];
    const float* conv_enc_b = (const float*)d_in[4];
    const float* lin_enc_w  = (const float*)d_in[5];
    const float* lin_enc_b  = (const float*)d_in[6];
    const float* bias_enc_w = (const float*)d_in[7];
    const float* bias_enc_b = (const float*)d_in[8];
    const float* gcn_w1     = (const float*)d_in[9];
    const float* gcn_w2     = (const float*)d_in[10];
    const float* conv_dec_w = (const float*)d_in[11];
    const float* conv_dec_b = (const float*)d_in[12];
    const float* lin_dec_w  = (const float*)d_in[13];
    const float* lin_dec_b  = (const float*)d_in[14];
    const float* bias_dec_w = (const float*)d_in[15];
    const float* bias_dec_b = (const float*)d_in[16];
    const float* embed_tab  = (const float*)d_in[17];
    const int*   adj        = (const int*)d_in[18];
    const int*   node_prims = (const int*)d_in[19];
    float* out = (float*)d_out;

    (void)in_sizes; (void)n_in; (void)out_size;

    const int DEC_SMEM = (128 * 104 + 2 * 64 * 104) * 4;   // 106496 B
    static int smem_set = 0;
    if (!smem_set) {
        cudaFuncSetAttribute(k_dec_tf32, cudaFuncAttributeMaxDynamicSharedMemorySize, DEC_SMEM);
        smem_set = 1;
    }

    k_prep_both<<<dim3(160, 32), 256>>>(conv_enc_w, lin_enc_w);                      // 0
    k_init_dinv<<<N_NODE, 256>>>(conv_enc_b, lin_enc_b, embed_tab, node_prims, adj); // 1
    k_enc_tf32<<<dim3(8, 76), 256>>>(conv_w, lin_w);                                 // 2 (conv+lin)
    // 3: PROBE — spmm on stale g_t1; g_h fully overwritten by the real
    // spmm(0) below before its first read (gcn_mm sel=1). Deterministic.
    k_spmm<<<129, dim3(96, 4)>>>(adj, 0);                                            // 3 <- profiled
    k_bias_enc<<<32, 256>>>(bias_w, bias_enc_w, bias_enc_b);                         // 4

    k_gcn_mm<<<33, 384>>>(gcn_w1, 0);
    k_spmm<<<129, dim3(96, 4)>>>(adj, 0);
    k_gcn_mm<<<33, 384>>>(gcn_w2, 1);
    k_spmm<<<129, dim3(96, 4)>>>(adj, 1);

    k_dec_tf32<<<dim3(72, 4), 256, DEC_SMEM>>>(conv_dec_w, conv_dec_b, out, 36864, 1, 0, (long long)OUT_OC, 8);
    k_dec_tf32<<<dim3(64, 2), 256, DEC_SMEM>>>(lin_dec_w, lin_dec_b, out, 4096, 513, 1, (long long)OUT_OL, 1);
    k_dec_bias<<<256, 96>>>(bias_dec_w, bias_dec_b, out);
}

// round 14
// speedup vs baseline: 1.0140x; 1.0140x over previous
#include <cuda_runtime.h>
#include <cuda_bf16.h>

#define N_NODE 1025
#define F3     96
#define KCONV  36864
#define KLIN   4096
#define OUT_OC 0
#define OUT_OL 18874368
#define OUT_OB 19922944
#define AROWS  1056            // adjF rows padded (33*32)
#define APITCH 1152            // adjF col pitch padded (36*32)

// ---------------- scratch ----------------------------------------------------
__device__ float g_encG[32 * KCONV];   // conv enc weights gathered, [h][K]
__device__ float g_linG[32 * KLIN];    // lin  enc weights gathered, [h][K]
__device__ float g_feats[N_NODE * F3];
__device__ float g_dinv[N_NODE];
__device__ float g_adjF[AROWS * APITCH]; // dinv[r]*(adj+I); pads stay 0 (static init)
__device__ float g_t1[APITCH * F3];    // rows 1025.. stay 0 (static init)
__device__ float g_h[N_NODE * F3];
__device__ float g_t2[APITCH * F3];    // rows 1025.. stay 0
__device__ float g_x[N_NODE * F3];

__device__ __forceinline__ int conv_idx(int t) {
    int r = t / 9, s = t - r * 9;
    int a = r >> 6, b = r & 63;
    return a * 1152 + b * 9 + s;
}
__device__ __forceinline__ int lin_idx(int t) {
    return ((t >> 6) << 7) + (t & 63);
}

__device__ __forceinline__ void mma_tf32(float c[4], const unsigned a[4], const unsigned b[2]) {
    asm volatile("mma.sync.aligned.m16n8k8.row.col.f32.tf32.tf32.f32 "
                 "{%0,%1,%2,%3}, {%4,%5,%6,%7}, {%8,%9}, {%0,%1,%2,%3};"
                 : "+f"(c[0]), "+f"(c[1]), "+f"(c[2]), "+f"(c[3])
                 : "r"(a[0]), "r"(a[1]), "r"(a[2]), "r"(a[3]),
                   "r"(b[0]), "r"(b[1]));
}

__device__ __forceinline__ void cp16(unsigned dst_smem, const void* src) {
    asm volatile("cp.async.cg.shared.global [%0], [%1], 16;" :: "r"(dst_smem), "l"(src));
}

// ---------------- 1. gather BOTH encoder weight sets ------------------------
__global__ void k_prep_both(const float* __restrict__ Wc, const float* __restrict__ Wl) {
    int h = blockIdx.y;
    if (blockIdx.x < 144) {
        int t = blockIdx.x * 256 + threadIdx.x;
        g_encG[h * KCONV + t] = Wc[h * 147456 + conv_idx(t)];
    } else {
        int t = (blockIdx.x - 144) * 256 + threadIdx.x;
        g_linG[h * KLIN + t] = Wl[h * 16384 + lin_idx(t)];
    }
}

// ---------------- 2. init feats + dinv + adjF (fused) -----------------------
__global__ void k_init_dinv(const float* __restrict__ ceb, const float* __restrict__ leb,
                            const float* __restrict__ emb, const int* __restrict__ prims,
                            const int* __restrict__ adj) {
    int i = blockIdx.x;

    int e = i * 256 + threadIdx.x;
    if (e < N_NODE * F3) {
        int row = e / F3, c = e - row * F3;
        float v;
        if (row == 0) v = 1.0f;
        else {
            int ii = row - 1;
            if (c >= 64)      v = emb[prims[ii] * 32 + (c - 64)];
            else {
                int h = c & 31;
                if (ii < 512)      v = ceb[h];
                else if (ii < 768) v = leb[h];
                else               v = 0.0f;
            }
        }
        g_feats[e] = v;
    }

    __shared__ int red[256];
    __shared__ float sdinv;
    int s = 0;
    for (int j = threadIdx.x; j < N_NODE; j += 256) s += adj[i * N_NODE + j];
    red[threadIdx.x] = s;
    __syncthreads();
    for (int off = 128; off > 0; off >>= 1) {
        if (threadIdx.x < off) red[threadIdx.x] += red[threadIdx.x + off];
        __syncthreads();
    }
    if (threadIdx.x == 0) {
        float d = rsqrtf((float)(red[0] + 1));
        g_dinv[i] = d;
        sdinv = d;
    }
    __syncthreads();
    float dv = sdinv;
    // adjF row: dinv[r]*(adj[r][l] + I)
    for (int l = threadIdx.x; l < N_NODE; l += 256) {
        float a = (float)adj[i * N_NODE + l] + (l == i ? 1.0f : 0.0f);
        g_adjF[i * APITCH + l] = dv * a;
    }
}

// ---------------- 4. encoder GEMM, tf32 + cp.async (conv+lin merged) --------
__global__ __launch_bounds__(256) void k_enc_tf32(const float* __restrict__ Ac,
                                                  const float* __restrict__ Al) {
    __shared__ unsigned As[3][64 * 40];
    __shared__ unsigned Bs[3][32 * 40];

    const float* A;
    const float* B;
    int K, featrow0, rowb, kbase;
    if (blockIdx.y < 72) {
        A = Ac; B = g_encG; K = KCONV; featrow0 = 1;
        rowb = blockIdx.x * 64;
        kbase = blockIdx.y * 512;
    } else {
        A = Al; B = g_linG; K = KLIN; featrow0 = 513;
        int id = (blockIdx.y - 72) * 8 + blockIdx.x;
        rowb = (id & 3) * 64;
        kbase = (id >> 2) * 512;
    }

    int tid = threadIdx.x;
    int warp = tid >> 5, lane = tid & 31;
    int g = lane >> 2, tg = lane & 3;
    int wm0 = (warp >> 1) * 16;
    int wn0 = (warp & 1) * 16;

    int mA0 = tid >> 3,            kqA0 = tid & 7;
    int mA1 = (tid + 256) >> 3,    kqA1 = (tid + 256) & 7;
    int mB  = tid >> 3,            kqB  = tid & 7;

    unsigned sA0[3], sA1[3], sB[3];
#pragma unroll
    for (int b = 0; b < 3; b++) {
        sA0[b] = (unsigned)__cvta_generic_to_shared(&As[b][mA0 * 40 + kqA0 * 4]);
        sA1[b] = (unsigned)__cvta_generic_to_shared(&As[b][mA1 * 40 + kqA1 * 4]);
        sB[b]  = (unsigned)__cvta_generic_to_shared(&Bs[b][mB * 40 + kqB * 4]);
    }

    const int NC = 16;
    auto issue = [&](int c) {
        int k0 = kbase + c * 32;
        int buf = c % 3;
        cp16(sA0[buf], &A[(rowb + mA0) * K + k0 + kqA0 * 4]);
        cp16(sA1[buf], &A[(rowb + mA1) * K + k0 + kqA1 * 4]);
        cp16(sB[buf],  &B[mB * K + k0 + kqB * 4]);
        asm volatile("cp.async.commit_group;");
    };

    issue(0);
    issue(1);

    float acc[2][4] = {};

    for (int c = 0; c < NC; c++) {
        if (c + 2 < NC) {
            issue(c + 2);
            asm volatile("cp.async.wait_group 2;");
        } else if (c + 1 < NC) {
            asm volatile("cp.async.wait_group 1;");
        } else {
            asm volatile("cp.async.wait_group 0;");
        }
        __syncthreads();

        const unsigned* Ab = As[c % 3];
        const unsigned* Bb = Bs[c % 3];
#pragma unroll
        for (int ks = 0; ks < 4; ks++) {
            int kk = ks * 8;
            unsigned a[4], b[2][2];
            a[0] = Ab[(wm0 + g) * 40 + kk + tg];
            a[1] = Ab[(wm0 + g + 8) * 40 + kk + tg];
            a[2] = Ab[(wm0 + g) * 40 + kk + tg + 4];
            a[3] = Ab[(wm0 + g + 8) * 40 + kk + tg + 4];
#pragma unroll
            for (int nt = 0; nt < 2; nt++) {
                b[nt][0] = Bb[(wn0 + nt * 8 + g) * 40 + kk + tg];
                b[nt][1] = Bb[(wn0 + nt * 8 + g) * 40 + kk + tg + 4];
            }
#pragma unroll
            for (int nt = 0; nt < 2; nt++) mma_tf32(acc[nt], a, b[nt]);
        }
        __syncthreads();
    }

#pragma unroll
    for (int nt = 0; nt < 2; nt++) {
        int h = wn0 + nt * 8 + 2 * tg;
        int r0 = featrow0 + rowb + wm0 + g;
        atomicAdd(&g_feats[r0 * F3 + h],          acc[nt][0]);
        atomicAdd(&g_feats[r0 * F3 + h + 1],      acc[nt][1]);
        atomicAdd(&g_feats[r0 * F3 + 32 + h],     acc[nt][0]);
        atomicAdd(&g_feats[r0 * F3 + 32 + h + 1], acc[nt][1]);
        int r1 = r0 + 8;
        atomicAdd(&g_feats[r1 * F3 + h],          acc[nt][2]);
        atomicAdd(&g_feats[r1 * F3 + h + 1],      acc[nt][3]);
        atomicAdd(&g_feats[r1 * F3 + 32 + h],     acc[nt][2]);
        atomicAdd(&g_feats[r1 * F3 + 32 + h + 1], acc[nt][3]);
    }
}

// ---------------- 5. bias encoder -------------------------------------------
__global__ void k_bias_enc(const float* __restrict__ bw, const float* __restrict__ Wb,
                           const float* __restrict__ bb) {
    __shared__ float sW[32 * 65];
    __shared__ float sB[8 * 64];
    int tid = threadIdx.x;
    for (int e = tid; e < 32 * 64; e += 256) {
        int hh = e >> 6, t = e & 63;
        sW[hh * 65 + t] = Wb[hh * 128 + t];
    }
    int ibase = blockIdx.x * 8;
    for (int e = tid; e < 8 * 64; e += 256) sB[e] = bw[ibase * 64 + e];
    __syncthreads();
    int h = tid & 31, ii = tid >> 5;
    float acc = 0.0f;
#pragma unroll
    for (int t = 0; t < 64; t++) acc += sB[ii * 64 + t] * sW[h * 65 + t];
    acc += bb[h];
    int row = 769 + ibase + ii;
    g_feats[row * F3 + h] = acc;
    g_feats[row * F3 + 32 + h] = acc;
}

// ---------------- 6. GCN dense GEMM (384 threads, 32 rows/block) ------------
__global__ __launch_bounds__(384) void k_gcn_mm(const float* __restrict__ W, int sel) {
    __shared__ float ws[96 * 96];
    __shared__ float fr[32 * 96];
    const float* __restrict__ in = sel ? g_h : g_feats;
    float* __restrict__ out = sel ? g_t2 : g_t1;
    int tid = threadIdx.x;
    int j = tid % 96, q = tid / 96;
    for (int e = tid; e < 96 * 96; e += 384) ws[e] = W[e];
    int rb = blockIdx.x * 32;
    for (int e = tid; e < 32 * 96; e += 384) {
        int rr = e / 96, c = e - rr * 96;
        int row = rb + rr;
        fr[e] = (row < N_NODE) ? in[row * 96 + c] : 0.0f;
    }
    __syncthreads();
#pragma unroll
    for (int rr8 = 0; rr8 < 8; rr8++) {
        int rr = q * 8 + rr8;
        int row = rb + rr;
        if (row < N_NODE) {
            float acc = 0.0f;
#pragma unroll 8
            for (int k = 0; k < 96; k++) acc += fr[rr * 96 + k] * ws[k * 96 + j];
            out[row * 96 + j] = g_dinv[row] * acc;
        }
    }
}

// ---------------- 7. SpMM as tf32 GEMM: out = adjF @ t ----------------------
// Grid 33, block 256. Block = 32 M x 96 N, K=1152 in 36 cp.async chunks.
// 8 warps = 2M x 4N (warp 16M x 24N = 3 n-tiles). Smem A [m][40], T [k][104].
__global__ __launch_bounds__(256) void k_spmm_tf32(int sel) {
    __shared__ unsigned As[2][32 * 40];
    __shared__ unsigned Ts[2][32 * 104];
    const float* __restrict__ ts = sel ? g_t2 : g_t1;
    float* __restrict__ out = sel ? g_x : g_h;

    int tid = threadIdx.x;
    int warp = tid >> 5, lane = tid & 31;
    int g = lane >> 2, tg = lane & 3;
    int wm0 = (warp >> 2) * 16;      // 0 or 16
    int wn0 = (warp & 3) * 24;       // 0,24,48,72
    int rowb = blockIdx.x * 32;

    // cp assignments: A 256 f4 (1/thread), T 768 f4 (3/thread)
    int ar = tid >> 3, ak = tid & 7;
    int trr[3], tcc[3];
    unsigned adst[2], tdst[2][3];
#pragma unroll
    for (int b = 0; b < 2; b++)
        adst[b] = (unsigned)__cvta_generic_to_shared(&As[b][ar * 40 + ak * 4]);
#pragma unroll
    for (int i = 0; i < 3; i++) {
        int e = tid + i * 256;
        trr[i] = e / 24; tcc[i] = e - trr[i] * 24;
#pragma unroll
        for (int b = 0; b < 2; b++)
            tdst[b][i] = (unsigned)__cvta_generic_to_shared(&Ts[b][trr[i] * 104 + tcc[i] * 4]);
    }

    const int NC = 36;
    auto issue = [&](int c) {
        int buf = c & 1;
        int k0 = c * 32;
        cp16(adst[buf], &g_adjF[(rowb + ar) * APITCH + k0 + ak * 4]);
#pragma unroll
        for (int i = 0; i < 3; i++)
            cp16(tdst[buf][i], &ts[(k0 + trr[i]) * 96 + tcc[i] * 4]);
        asm volatile("cp.async.commit_group;");
    };

    issue(0);

    float acc[3][4] = {};
    for (int c = 0; c < NC; c++) {
        if (c + 1 < NC) {
            issue(c + 1);
            asm volatile("cp.async.wait_group 1;");
        } else {
            asm volatile("cp.async.wait_group 0;");
        }
        __syncthreads();

        const unsigned* Ab = As[c & 1];
        const unsigned* Tb = Ts[c & 1];
#pragma unroll
        for (int ks = 0; ks < 4; ks++) {
            int kk = ks * 8;
            unsigned a[4], b[3][2];
            a[0] = Ab[(wm0 + g) * 40 + kk + tg];
            a[1] = Ab[(wm0 + g + 8) * 40 + kk + tg];
            a[2] = Ab[(wm0 + g) * 40 + kk + tg + 4];
            a[3] = Ab[(wm0 + g + 8) * 40 + kk + tg + 4];
#pragma unroll
            for (int ni = 0; ni < 3; ni++) {
                int n = wn0 + ni * 8 + g;
                b[ni][0] = Tb[(kk + tg) * 104 + n];
                b[ni][1] = Tb[(kk + tg + 4) * 104 + n];
            }
#pragma unroll
            for (int ni = 0; ni < 3; ni++) mma_tf32(acc[ni], a, b[ni]);
        }
        __syncthreads();
    }

    int r0 = rowb + wm0 + g;
    int r1 = r0 + 8;
#pragma unroll
    for (int ni = 0; ni < 3; ni++) {
        int col = wn0 + ni * 8 + 2 * tg;
        float2 v0 = make_float2(acc[ni][0], acc[ni][1]);
        float2 v1 = make_float2(acc[ni][2], acc[ni][3]);
        if (!sel) {
            v0.x = fmaxf(v0.x, 0.0f); v0.y = fmaxf(v0.y, 0.0f);
            v1.x = fmaxf(v1.x, 0.0f); v1.y = fmaxf(v1.y, 0.0f);
        }
        if (r0 < N_NODE) *(float2*)&out[r0 * 96 + col] = v0;
        if (r1 < N_NODE) *(float2*)&out[r1 * 96 + col] = v1;
    }
}

// ---------------- 8. decoder GEMM: 128M x (jt*64)N, cp.async W --------------
__global__ __launch_bounds__(256) void k_dec_tf32(const float* __restrict__ Wd,
                                                  const float* __restrict__ bd,
                                                  float* __restrict__ out,
                                                  int Ntot, int xrow0, int mode,
                                                  long long outoff, int jt) {
    extern __shared__ unsigned smem[];
    unsigned* Xs = smem;                      // [128][104]
    unsigned* Ws0 = smem + 128 * 104;         // [2][64][104]

    int tid = threadIdx.x;
    int warp = tid >> 5, lane = tid & 31;
    int g = lane >> 2, tg = lane & 3;
    int wm0 = (warp >> 1) * 32;
    int wn0 = (warp & 1) * 32;
    int nbase = blockIdx.x * (jt * 64);
    int ibase = blockIdx.y * 128;

    int wrow[6], wk4[6];
    unsigned wdst[2][6];
#pragma unroll
    for (int i = 0; i < 6; i++) {
        int e = tid + i * 256;
        wrow[i] = e / 24;
        wk4[i] = e - wrow[i] * 24;
        wdst[0][i] = (unsigned)__cvta_generic_to_shared(&Ws0[wrow[i] * 104 + wk4[i] * 4]);
        wdst[1][i] = (unsigned)__cvta_generic_to_shared(&Ws0[64 * 104 + wrow[i] * 104 + wk4[i] * 4]);
    }
    auto issue_w = [&](int j) {
        int buf = j & 1;
#pragma unroll
        for (int i = 0; i < 6; i++) {
            int tglob = nbase + j * 64 + wrow[i];
            int id = (mode == 0) ? conv_idx(tglob) : lin_idx(tglob);
            cp16(wdst[buf][i], &Wd[id * 96 + wk4[i] * 4]);
        }
        asm volatile("cp.async.commit_group;");
    };

    issue_w(0);

#pragma unroll
    for (int i = 0; i < 12; i++) {
        int e = tid + i * 256;
        int m = e / 24, k4 = e - m * 24;
        float4 v = *(const float4*)&g_x[(xrow0 + ibase + m) * 96 + k4 * 4];
        *(float4*)&Xs[m * 104 + k4 * 4] = *(float4*)&v;
    }

    for (int j = 0; j < jt; j++) {
        if (j + 1 < jt) {
            issue_w(j + 1);
            asm volatile("cp.async.wait_group 1;");
        } else {
            asm volatile("cp.async.wait_group 0;");
        }
        __syncthreads();

        int tb = nbase + j * 64;
        float bx[4], by[4];
#pragma unroll
        for (int ni = 0; ni < 4; ni++) {
            int ncol = wn0 + ni * 8 + 2 * tg;
            int t0 = tb + ncol;
            int i0 = (mode == 0) ? conv_idx(t0) : lin_idx(t0);
            int i1 = (mode == 0) ? conv_idx(t0 + 1) : lin_idx(t0 + 1);
            bx[ni] = bd[i0];
            by[ni] = bd[i1];
        }

        const unsigned* Wb = Ws0 + (j & 1) * (64 * 104);
        float acc[2][4][4] = {};
#pragma unroll
        for (int ks = 0; ks < 12; ks++) {
            int k0 = ks * 8;
            unsigned a[2][4], b[4][2];
#pragma unroll
            for (int mi = 0; mi < 2; mi++) {
                int m = wm0 + mi * 16 + g;
                a[mi][0] = Xs[m * 104 + k0 + tg];
                a[mi][1] = Xs[(m + 8) * 104 + k0 + tg];
                a[mi][2] = Xs[m * 104 + k0 + tg + 4];
                a[mi][3] = Xs[(m + 8) * 104 + k0 + tg + 4];
            }
#pragma unroll
            for (int ni = 0; ni < 4; ni++) {
                int n = wn0 + ni * 8 + g;
                b[ni][0] = Wb[n * 104 + k0 + tg];
                b[ni][1] = Wb[n * 104 + k0 + tg + 4];
            }
#pragma unroll
            for (int mi = 0; mi < 2; mi++)
#pragma unroll
                for (int ni = 0; ni < 4; ni++)
                    mma_tf32(acc[mi][ni], a[mi], b[ni]);
        }

#pragma unroll
        for (int mi = 0; mi < 2; mi++) {
            int row0 = ibase + wm0 + mi * 16 + g;
#pragma unroll
            for (int ni = 0; ni < 4; ni++) {
                int col = tb + wn0 + ni * 8 + 2 * tg;
                float2 v0 = make_float2(acc[mi][ni][0] + bx[ni], acc[mi][ni][1] + by[ni]);
                float2 v1 = make_float2(acc[mi][ni][2] + bx[ni], acc[mi][ni][3] + by[ni]);
                *(float2*)&out[outoff + (long long)row0 * Ntot + col] = v0;
                *(float2*)&out[outoff + (long long)(row0 + 8) * Ntot + col] = v1;
            }
        }
        __syncthreads();
    }
}

// ---------------- 9. bias decoder (tiny) ------------------------------------
__global__ void k_dec_bias(const float* __restrict__ Wd, const float* __restrict__ bd,
                           float* __restrict__ out) {
    __shared__ float xr[96];
    int i = blockIdx.x;
    xr[threadIdx.x] = g_x[(769 + i) * 96 + threadIdx.x];
    __syncthreads();
    int t = threadIdx.x;
    if (t < 64) {
        float acc = 0.0f;
#pragma unroll 8
        for (int k = 0; k < 96; k++) acc += xr[k] * Wd[t * 96 + k];
        out[OUT_OB + i * 64 + t] = acc + bd[t];
    }
}

// ---------------- launch -----------------------------------------------------
extern "C" void kernel_launch(void* const* d_in, const int* in_sizes, int n_in,
                              void* d_out, int out_size) {
    const float* conv_w     = (const float*)d_in[0];
    const float* lin_w      = (const float*)d_in[1];
    const float* bias_w     = (const float*)d_in[2];
    const float* conv_enc_w = (const float*)d_in[3];
    const float* conv_enc_b = (const float*)d_in[4];
    const float* lin_enc_w  = (const float*)d_in[5];
    const float* lin_enc_b  = (const float*)d_in[6];
    const float* bias_enc_w = (const float*)d_in[7];
    const float* bias_enc_b = (const float*)d_in[8];
    const float* gcn_w1     = (const float*)d_in[9];
    const float* gcn_w2     = (const float*)d_in[10];
    const float* conv_dec_w = (const float*)d_in[11];
    const float* conv_dec_b = (const float*)d_in[12];
    const float* lin_dec_w  = (const float*)d_in[13];
    const float* lin_dec_b  = (const float*)d_in[14];
    const float* bias_dec_w = (const float*)d_in[15];
    const float* bias_dec_b = (const float*)d_in[16];
    const float* embed_tab  = (const float*)d_in[17];
    const int*   adj        = (const int*)d_in[18];
    const int*   node_prims = (const int*)d_in[19];
    float* out = (float*)d_out;

    (void)in_sizes; (void)n_in; (void)out_size;

    const int DEC_SMEM = (128 * 104 + 2 * 64 * 104) * 4;   // 106496 B
    static int smem_set = 0;
    if (!smem_set) {
        cudaFuncSetAttribute(k_dec_tf32, cudaFuncAttributeMaxDynamicSharedMemorySize, DEC_SMEM);
        smem_set = 1;
    }

    k_prep_both<<<dim3(160, 32), 256>>>(conv_enc_w, lin_enc_w);                      // 0
    k_init_dinv<<<N_NODE, 256>>>(conv_enc_b, lin_enc_b, embed_tab, node_prims, adj); // 1
    k_enc_tf32<<<dim3(8, 76), 256>>>(conv_w, lin_w);                                 // 2
    // 3: PROBE — new spmm on stale g_t1 -> g_h; fully overwritten by the real
    // spmm(0) below before g_h's first consumer (gcn_mm sel=1). Deterministic.
    k_spmm_tf32<<<33, 256>>>(0);                                                     // 3 <- profiled
    k_bias_enc<<<32, 256>>>(bias_w, bias_enc_w, bias_enc_b);                         // 4

    k_gcn_mm<<<33, 384>>>(gcn_w1, 0);
    k_spmm_tf32<<<33, 256>>>(0);
    k_gcn_mm<<<33, 384>>>(gcn_w2, 1);
    k_spmm_tf32<<<33, 256>>>(1);

    k_dec_tf32<<<dim3(72, 4), 256, DEC_SMEM>>>(conv_dec_w, conv_dec_b, out, 36864, 1, 0, (long long)OUT_OC, 8);
    k_dec_tf32<<<dim3(64, 2), 256, DEC_SMEM>>>(lin_dec_w, lin_dec_b, out, 4096, 513, 1, (long long)OUT_OL, 1);
    k_dec_bias<<<256, 96>>>(bias_dec_w, bias_dec_b, out);
}

// round 16
// speedup vs baseline: 1.8659x; 1.8401x over previous
#include <cuda_runtime.h>
#include <cuda_bf16.h>

#define N_NODE 1025
#define F3     96
#define KCONV  36864
#define KLIN   4096
#define OUT_OC 0
#define OUT_OL 18874368
#define OUT_OB 19922944
#define AROWS  1056            // adjF rows padded (33*32)
#define APITCH 1152            // adjF col pitch padded (36*32)

// ---------------- scratch ----------------------------------------------------
__device__ float g_encG[32 * KCONV];   // conv enc weights gathered, [h][K]
__device__ float g_linG[32 * KLIN];    // lin  enc weights gathered, [h][K]
__device__ float g_feats[N_NODE * F3];
__device__ float g_dinv[N_NODE];
__device__ float g_adjF[AROWS * APITCH]; // dinv[r]*(adj+I); pads stay 0 (static init)
__device__ float g_t1[APITCH * F3];    // rows 1025.. stay 0 (static init)
__device__ float g_h[N_NODE * F3];     // PRE-relu accumulator (zeroed per launch)
__device__ float g_t2[APITCH * F3];    // rows 1025.. stay 0
__device__ float g_x[N_NODE * F3];     // accumulator (zeroed per launch)

__device__ __forceinline__ int conv_idx(int t) {
    int r = t / 9, s = t - r * 9;
    int a = r >> 6, b = r & 63;
    return a * 1152 + b * 9 + s;
}
__device__ __forceinline__ int lin_idx(int t) {
    return ((t >> 6) << 7) + (t & 63);
}

__device__ __forceinline__ void mma_tf32(float c[4], const unsigned a[4], const unsigned b[2]) {
    asm volatile("mma.sync.aligned.m16n8k8.row.col.f32.tf32.tf32.f32 "
                 "{%0,%1,%2,%3}, {%4,%5,%6,%7}, {%8,%9}, {%0,%1,%2,%3};"
                 : "+f"(c[0]), "+f"(c[1]), "+f"(c[2]), "+f"(c[3])
                 : "r"(a[0]), "r"(a[1]), "r"(a[2]), "r"(a[3]),
                   "r"(b[0]), "r"(b[1]));
}

__device__ __forceinline__ void cp16(unsigned dst_smem, const void* src) {
    asm volatile("cp.async.cg.shared.global [%0], [%1], 16;" :: "r"(dst_smem), "l"(src));
}

// ---------------- 1. gather BOTH encoder weight sets ------------------------
__global__ void k_prep_both(const float* __restrict__ Wc, const float* __restrict__ Wl) {
    int h = blockIdx.y;
    if (blockIdx.x < 144) {
        int t = blockIdx.x * 256 + threadIdx.x;
        g_encG[h * KCONV + t] = Wc[h * 147456 + conv_idx(t)];
    } else {
        int t = (blockIdx.x - 144) * 256 + threadIdx.x;
        g_linG[h * KLIN + t] = Wl[h * 16384 + lin_idx(t)];
    }
}

// ---------------- 2. init feats + dinv + adjF + zero h/x (fused) ------------
__global__ void k_init_dinv(const float* __restrict__ ceb, const float* __restrict__ leb,
                            const float* __restrict__ emb, const int* __restrict__ prims,
                            const int* __restrict__ adj) {
    int i = blockIdx.x;

    int e = i * 256 + threadIdx.x;
    if (e < N_NODE * F3) {
        int row = e / F3, c = e - row * F3;
        float v;
        if (row == 0) v = 1.0f;
        else {
            int ii = row - 1;
            if (c >= 64)      v = emb[prims[ii] * 32 + (c - 64)];
            else {
                int h = c & 31;
                if (ii < 512)      v = ceb[h];
                else if (ii < 768) v = leb[h];
                else               v = 0.0f;
            }
        }
        g_feats[e] = v;
    }

    // zero accumulators for split-K spmm (row i of each)
    for (int c = threadIdx.x; c < 96; c += 256) {
        g_h[i * 96 + c] = 0.0f;
        g_x[i * 96 + c] = 0.0f;
    }

    __shared__ int red[256];
    __shared__ float sdinv;
    int s = 0;
    for (int j = threadIdx.x; j < N_NODE; j += 256) s += adj[i * N_NODE + j];
    red[threadIdx.x] = s;
    __syncthreads();
    for (int off = 128; off > 0; off >>= 1) {
        if (threadIdx.x < off) red[threadIdx.x] += red[threadIdx.x + off];
        __syncthreads();
    }
    if (threadIdx.x == 0) {
        float d = rsqrtf((float)(red[0] + 1));
        g_dinv[i] = d;
        sdinv = d;
    }
    __syncthreads();
    float dv = sdinv;
    for (int l = threadIdx.x; l < N_NODE; l += 256) {
        float a = (float)adj[i * N_NODE + l] + (l == i ? 1.0f : 0.0f);
        g_adjF[i * APITCH + l] = dv * a;
    }
}

// ---------------- 4. encoder GEMM + bias encoder (merged) -------------------
// y < 72 : conv tile.  y in [72,76): lin tile.  y in [76,80): bias-enc block.
__global__ __launch_bounds__(256) void k_enc_tf32(const float* __restrict__ Ac,
                                                  const float* __restrict__ Al,
                                                  const float* __restrict__ bw,
                                                  const float* __restrict__ Wb,
                                                  const float* __restrict__ bb) {
    if (blockIdx.y >= 76) {
        // ---- bias encoder path (32 blocks) ----
        __shared__ float sW[32 * 65];
        __shared__ float sB[8 * 64];
        int bid = (blockIdx.y - 76) * 8 + blockIdx.x;
        int tid = threadIdx.x;
        for (int e = tid; e < 32 * 64; e += 256) {
            int hh = e >> 6, t = e & 63;
            sW[hh * 65 + t] = Wb[hh * 128 + t];
        }
        int ibase = bid * 8;
        for (int e = tid; e < 8 * 64; e += 256) sB[e] = bw[ibase * 64 + e];
        __syncthreads();
        int h = tid & 31, ii = tid >> 5;
        float acc = 0.0f;
#pragma unroll
        for (int t = 0; t < 64; t++) acc += sB[ii * 64 + t] * sW[h * 65 + t];
        acc += bb[h];
        int row = 769 + ibase + ii;
        g_feats[row * F3 + h] = acc;
        g_feats[row * F3 + 32 + h] = acc;
        return;
    }

    __shared__ unsigned As[3][64 * 40];
    __shared__ unsigned Bs[3][32 * 40];

    const float* A;
    const float* B;
    int K, featrow0, rowb, kbase;
    if (blockIdx.y < 72) {
        A = Ac; B = g_encG; K = KCONV; featrow0 = 1;
        rowb = blockIdx.x * 64;
        kbase = blockIdx.y * 512;
    } else {
        A = Al; B = g_linG; K = KLIN; featrow0 = 513;
        int id = (blockIdx.y - 72) * 8 + blockIdx.x;
        rowb = (id & 3) * 64;
        kbase = (id >> 2) * 512;
    }

    int tid = threadIdx.x;
    int warp = tid >> 5, lane = tid & 31;
    int g = lane >> 2, tg = lane & 3;
    int wm0 = (warp >> 1) * 16;
    int wn0 = (warp & 1) * 16;

    int mA0 = tid >> 3,            kqA0 = tid & 7;
    int mA1 = (tid + 256) >> 3,    kqA1 = (tid + 256) & 7;
    int mB  = tid >> 3,            kqB  = tid & 7;

    unsigned sA0[3], sA1[3], sB[3];
#pragma unroll
    for (int b = 0; b < 3; b++) {
        sA0[b] = (unsigned)__cvta_generic_to_shared(&As[b][mA0 * 40 + kqA0 * 4]);
        sA1[b] = (unsigned)__cvta_generic_to_shared(&As[b][mA1 * 40 + kqA1 * 4]);
        sB[b]  = (unsigned)__cvta_generic_to_shared(&Bs[b][mB * 40 + kqB * 4]);
    }

    const int NC = 16;
    auto issue = [&](int c) {
        int k0 = kbase + c * 32;
        int buf = c % 3;
        cp16(sA0[buf], &A[(rowb + mA0) * K + k0 + kqA0 * 4]);
        cp16(sA1[buf], &A[(rowb + mA1) * K + k0 + kqA1 * 4]);
        cp16(sB[buf],  &B[mB * K + k0 + kqB * 4]);
        asm volatile("cp.async.commit_group;");
    };

    issue(0);
    issue(1);

    float acc[2][4] = {};

    for (int c = 0; c < NC; c++) {
        if (c + 2 < NC) {
            issue(c + 2);
            asm volatile("cp.async.wait_group 2;");
        } else if (c + 1 < NC) {
            asm volatile("cp.async.wait_group 1;");
        } else {
            asm volatile("cp.async.wait_group 0;");
        }
        __syncthreads();

        const unsigned* Ab = As[c % 3];
        const unsigned* Bb = Bs[c % 3];
#pragma unroll
        for (int ks = 0; ks < 4; ks++) {
            int kk = ks * 8;
            unsigned a[4], b[2][2];
            a[0] = Ab[(wm0 + g) * 40 + kk + tg];
            a[1] = Ab[(wm0 + g + 8) * 40 + kk + tg];
            a[2] = Ab[(wm0 + g) * 40 + kk + tg + 4];
            a[3] = Ab[(wm0 + g + 8) * 40 + kk + tg + 4];
#pragma unroll
            for (int nt = 0; nt < 2; nt++) {
                b[nt][0] = Bb[(wn0 + nt * 8 + g) * 40 + kk + tg];
                b[nt][1] = Bb[(wn0 + nt * 8 + g) * 40 + kk + tg + 4];
            }
#pragma unroll
            for (int nt = 0; nt < 2; nt++) mma_tf32(acc[nt], a, b[nt]);
        }
        __syncthreads();
    }

#pragma unroll
    for (int nt = 0; nt < 2; nt++) {
        int h = wn0 + nt * 8 + 2 * tg;
        int r0 = featrow0 + rowb + wm0 + g;
        atomicAdd(&g_feats[r0 * F3 + h],          acc[nt][0]);
        atomicAdd(&g_feats[r0 * F3 + h + 1],      acc[nt][1]);
        atomicAdd(&g_feats[r0 * F3 + 32 + h],     acc[nt][0]);
        atomicAdd(&g_feats[r0 * F3 + 32 + h + 1], acc[nt][1]);
        int r1 = r0 + 8;
        atomicAdd(&g_feats[r1 * F3 + h],          acc[nt][2]);
        atomicAdd(&g_feats[r1 * F3 + h + 1],      acc[nt][3]);
        atomicAdd(&g_feats[r1 * F3 + 32 + h],     acc[nt][2]);
        atomicAdd(&g_feats[r1 * F3 + 32 + h + 1], acc[nt][3]);
    }
}

// ---------------- 6. GCN dense GEMM (relu-on-load for sel=1) ----------------
__global__ __launch_bounds__(384) void k_gcn_mm(const float* __restrict__ W, int sel) {
    __shared__ float ws[96 * 96];
    __shared__ float fr[32 * 96];
    const float* __restrict__ in = sel ? g_h : g_feats;
    float* __restrict__ out = sel ? g_t2 : g_t1;
    int tid = threadIdx.x;
    int j = tid % 96, q = tid / 96;
    for (int e = tid; e < 96 * 96; e += 384) ws[e] = W[e];
    int rb = blockIdx.x * 32;
    for (int e = tid; e < 32 * 96; e += 384) {
        int rr = e / 96, c = e - rr * 96;
        int row = rb + rr;
        float v = (row < N_NODE) ? in[row * 96 + c] : 0.0f;
        if (sel) v = fmaxf(v, 0.0f);      // relu(An@t1) applied here
        fr[e] = v;
    }
    __syncthreads();
#pragma unroll
    for (int rr8 = 0; rr8 < 8; rr8++) {
        int rr = q * 8 + rr8;
        int row = rb + rr;
        if (row < N_NODE) {
            float acc = 0.0f;
#pragma unroll 8
            for (int k = 0; k < 96; k++) acc += fr[rr * 96 + k] * ws[k * 96 + j];
            out[row * 96 + j] = g_dinv[row] * acc;
        }
    }
}

// ---------------- 7. SpMM as tf32 GEMM, split-K x4 --------------------------
// Grid (33, 4). Block = 32M x 96N, K slice of 288 (9 chunks of 32).
// Partial sums atomicAdd'ed into out (zeroed in k_init_dinv). No relu here.
__global__ __launch_bounds__(256) void k_spmm_tf32(int sel) {
    __shared__ unsigned As[2][32 * 40];
    __shared__ unsigned Ts[2][32 * 104];
    const float* __restrict__ ts = sel ? g_t2 : g_t1;
    float* __restrict__ out = sel ? g_x : g_h;

    int tid = threadIdx.x;
    int warp = tid >> 5, lane = tid & 31;
    int g = lane >> 2, tg = lane & 3;
    int wm0 = (warp >> 2) * 16;
    int wn0 = (warp & 3) * 24;
    int rowb = blockIdx.x * 32;
    int kbase = blockIdx.y * 288;

    int ar = tid >> 3, ak = tid & 7;
    int trr[3], tcc[3];
    unsigned adst[2], tdst[2][3];
#pragma unroll
    for (int b = 0; b < 2; b++)
        adst[b] = (unsigned)__cvta_generic_to_shared(&As[b][ar * 40 + ak * 4]);
#pragma unroll
    for (int i = 0; i < 3; i++) {
        int e = tid + i * 256;
        trr[i] = e / 24; tcc[i] = e - trr[i] * 24;
#pragma unroll
        for (int b = 0; b < 2; b++)
            tdst[b][i] = (unsigned)__cvta_generic_to_shared(&Ts[b][trr[i] * 104 + tcc[i] * 4]);
    }

    const int NC = 9;
    auto issue = [&](int c) {
        int buf = c & 1;
        int k0 = kbase + c * 32;
        cp16(adst[buf], &g_adjF[(rowb + ar) * APITCH + k0 + ak * 4]);
#pragma unroll
        for (int i = 0; i < 3; i++)
            cp16(tdst[buf][i], &ts[(k0 + trr[i]) * 96 + tcc[i] * 4]);
        asm volatile("cp.async.commit_group;");
    };

    issue(0);

    float acc[3][4] = {};
    for (int c = 0; c < NC; c++) {
        if (c + 1 < NC) {
            issue(c + 1);
            asm volatile("cp.async.wait_group 1;");
        } else {
            asm volatile("cp.async.wait_group 0;");
        }
        __syncthreads();

        const unsigned* Ab = As[c & 1];
        const unsigned* Tb = Ts[c & 1];
#pragma unroll
        for (int ks = 0; ks < 4; ks++) {
            int kk = ks * 8;
            unsigned a[4], b[3][2];
            a[0] = Ab[(wm0 + g) * 40 + kk + tg];
            a[1] = Ab[(wm0 + g + 8) * 40 + kk + tg];
            a[2] = Ab[(wm0 + g) * 40 + kk + tg + 4];
            a[3] = Ab[(wm0 + g + 8) * 40 + kk + tg + 4];
#pragma unroll
            for (int ni = 0; ni < 3; ni++) {
                int n = wn0 + ni * 8 + g;
                b[ni][0] = Tb[(kk + tg) * 104 + n];
                b[ni][1] = Tb[(kk + tg + 4) * 104 + n];
            }
#pragma unroll
            for (int ni = 0; ni < 3; ni++) mma_tf32(acc[ni], a, b[ni]);
        }
        __syncthreads();
    }

    int r0 = rowb + wm0 + g;
    int r1 = r0 + 8;
#pragma unroll
    for (int ni = 0; ni < 3; ni++) {
        int col = wn0 + ni * 8 + 2 * tg;
        if (r0 < N_NODE) {
            atomicAdd(&out[r0 * 96 + col],     acc[ni][0]);
            atomicAdd(&out[r0 * 96 + col + 1], acc[ni][1]);
        }
        if (r1 < N_NODE) {
            atomicAdd(&out[r1 * 96 + col],     acc[ni][2]);
            atomicAdd(&out[r1 * 96 + col + 1], acc[ni][3]);
        }
    }
}

// ---------------- 8. decoder GEMM: 128M x (jt*64)N, cp.async W --------------
__global__ __launch_bounds__(256) void k_dec_tf32(const float* __restrict__ Wd,
                                                  const float* __restrict__ bd,
                                                  float* __restrict__ out,
                                                  int Ntot, int xrow0, int mode,
                                                  long long outoff, int jt) {
    extern __shared__ unsigned smem[];
    unsigned* Xs = smem;                      // [128][104]
    unsigned* Ws0 = smem + 128 * 104;         // [2][64][104]

    int tid = threadIdx.x;
    int warp = tid >> 5, lane = tid & 31;
    int g = lane >> 2, tg = lane & 3;
    int wm0 = (warp >> 1) * 32;
    int wn0 = (warp & 1) * 32;
    int nbase = blockIdx.x * (jt * 64);
    int ibase = blockIdx.y * 128;

    int wrow[6], wk4[6];
    unsigned wdst[2][6];
#pragma unroll
    for (int i = 0; i < 6; i++) {
        int e = tid + i * 256;
        wrow[i] = e / 24;
        wk4[i] = e - wrow[i] * 24;
        wdst[0][i] = (unsigned)__cvta_generic_to_shared(&Ws0[wrow[i] * 104 + wk4[i] * 4]);
        wdst[1][i] = (unsigned)__cvta_generic_to_shared(&Ws0[64 * 104 + wrow[i] * 104 + wk4[i] * 4]);
    }
    auto issue_w = [&](int j) {
        int buf = j & 1;
#pragma unroll
        for (int i = 0; i < 6; i++) {
            int tglob = nbase + j * 64 + wrow[i];
            int id = (mode == 0) ? conv_idx(tglob) : lin_idx(tglob);
            cp16(wdst[buf][i], &Wd[id * 96 + wk4[i] * 4]);
        }
        asm volatile("cp.async.commit_group;");
    };

    issue_w(0);

#pragma unroll
    for (int i = 0; i < 12; i++) {
        int e = tid + i * 256;
        int m = e / 24, k4 = e - m * 24;
        float4 v = *(const float4*)&g_x[(xrow0 + ibase + m) * 96 + k4 * 4];
        *(float4*)&Xs[m * 104 + k4 * 4] = *(float4*)&v;
    }

    for (int j = 0; j < jt; j++) {
        if (j + 1 < jt) {
            issue_w(j + 1);
            asm volatile("cp.async.wait_group 1;");
        } else {
            asm volatile("cp.async.wait_group 0;");
        }
        __syncthreads();

        int tb = nbase + j * 64;
        float bx[4], by[4];
#pragma unroll
        for (int ni = 0; ni < 4; ni++) {
            int ncol = wn0 + ni * 8 + 2 * tg;
            int t0 = tb + ncol;
            int i0 = (mode == 0) ? conv_idx(t0) : lin_idx(t0);
            int i1 = (mode == 0) ? conv_idx(t0 + 1) : lin_idx(t0 + 1);
            bx[ni] = bd[i0];
            by[ni] = bd[i1];
        }

        const unsigned* Wb = Ws0 + (j & 1) * (64 * 104);
        float acc[2][4][4] = {};
#pragma unroll
        for (int ks = 0; ks < 12; ks++) {
            int k0 = ks * 8;
            unsigned a[2][4], b[4][2];
#pragma unroll
            for (int mi = 0; mi < 2; mi++) {
                int m = wm0 + mi * 16 + g;
                a[mi][0] = Xs[m * 104 + k0 + tg];
                a[mi][1] = Xs[(m + 8) * 104 + k0 + tg];
                a[mi][2] = Xs[m * 104 + k0 + tg + 4];
                a[mi][3] = Xs[(m + 8) * 104 + k0 + tg + 4];
            }
#pragma unroll
            for (int ni = 0; ni < 4; ni++) {
                int n = wn0 + ni * 8 + g;
                b[ni][0] = Wb[n * 104 + k0 + tg];
                b[ni][1] = Wb[n * 104 + k0 + tg + 4];
            }
#pragma unroll
            for (int mi = 0; mi < 2; mi++)
#pragma unroll
                for (int ni = 0; ni < 4; ni++)
                    mma_tf32(acc[mi][ni], a[mi], b[ni]);
        }

#pragma unroll
        for (int mi = 0; mi < 2; mi++) {
            int row0 = ibase + wm0 + mi * 16 + g;
#pragma unroll
            for (int ni = 0; ni < 4; ni++) {
                int col = tb + wn0 + ni * 8 + 2 * tg;
                float2 v0 = make_float2(acc[mi][ni][0] + bx[ni], acc[mi][ni][1] + by[ni]);
                float2 v1 = make_float2(acc[mi][ni][2] + bx[ni], acc[mi][ni][3] + by[ni]);
                *(float2*)&out[outoff + (long long)row0 * Ntot + col] = v0;
                *(float2*)&out[outoff + (long long)(row0 + 8) * Ntot + col] = v1;
            }
        }
        __syncthreads();
    }
}

// ---------------- 9. bias decoder (tiny) ------------------------------------
__global__ void k_dec_bias(const float* __restrict__ Wd, const float* __restrict__ bd,
                           float* __restrict__ out) {
    __shared__ float xr[96];
    int i = blockIdx.x;
    xr[threadIdx.x] = g_x[(769 + i) * 96 + threadIdx.x];
    __syncthreads();
    int t = threadIdx.x;
    if (t < 64) {
        float acc = 0.0f;
#pragma unroll 8
        for (int k = 0; k < 96; k++) acc += xr[k] * Wd[t * 96 + k];
        out[OUT_OB + i * 64 + t] = acc + bd[t];
    }
}

// ---------------- launch -----------------------------------------------------
extern "C" void kernel_launch(void* const* d_in, const int* in_sizes, int n_in,
                              void* d_out, int out_size) {
    const float* conv_w     = (const float*)d_in[0];
    const float* lin_w      = (const float*)d_in[1];
    const float* bias_w     = (const float*)d_in[2];
    const float* conv_enc_w = (const float*)d_in[3];
    const float* conv_enc_b = (const float*)d_in[4];
    const float* lin_enc_w  = (const float*)d_in[5];
    const float* lin_enc_b  = (const float*)d_in[6];
    const float* bias_enc_w = (const float*)d_in[7];
    const float* bias_enc_b = (const float*)d_in[8];
    const float* gcn_w1     = (const float*)d_in[9];
    const float* gcn_w2     = (const float*)d_in[10];
    const float* conv_dec_w = (const float*)d_in[11];
    const float* conv_dec_b = (const float*)d_in[12];
    const float* lin_dec_w  = (const float*)d_in[13];
    const float* lin_dec_b  = (const float*)d_in[14];
    const float* bias_dec_w = (const float*)d_in[15];
    const float* bias_dec_b = (const float*)d_in[16];
    const float* embed_tab  = (const float*)d_in[17];
    const int*   adj        = (const int*)d_in[18];
    const int*   node_prims = (const int*)d_in[19];
    float* out = (float*)d_out;

    (void)in_sizes; (void)n_in; (void)out_size;

    const int DEC_SMEM = (128 * 104 + 2 * 64 * 104) * 4;   // 106496 B
    static int smem_set = 0;
    if (!smem_set) {
        cudaFuncSetAttribute(k_dec_tf32, cudaFuncAttributeMaxDynamicSharedMemorySize, DEC_SMEM);
        smem_set = 1;
    }

    k_prep_both<<<dim3(160, 32), 256>>>(conv_enc_w, lin_enc_w);                      // 0
    k_init_dinv<<<N_NODE, 256>>>(conv_enc_b, lin_enc_b, embed_tab, node_prims, adj); // 1
    k_enc_tf32<<<dim3(8, 80), 256>>>(conv_w, lin_w, bias_w, bias_enc_w, bias_enc_b); // 2 (conv+lin+bias)
    k_gcn_mm<<<33, 384>>>(gcn_w1, 0);                                                // 3 <- profiled
    k_spmm_tf32<<<dim3(33, 4), 256>>>(0);
    k_gcn_mm<<<33, 384>>>(gcn_w2, 1);
    k_spmm_tf32<<<dim3(33, 4), 256>>>(1);

    k_dec_tf32<<<dim3(72, 4), 256, DEC_SMEM>>>(conv_dec_w, conv_dec_b, out, 36864, 1, 0, (long long)OUT_OC, 8);
    k_dec_tf32<<<dim3(64, 2), 256, DEC_SMEM>>>(lin_dec_w, lin_dec_b, out, 4096, 513, 1, (long long)OUT_OL, 1);
    k_dec_bias<<<256, 96>>>(bias_dec_w, bias_dec_b, out);
}

// round 17
// speedup vs baseline: 2.2660x; 1.2144x over previous
#include <cuda_runtime.h>
#include <cuda_bf16.h>

#define N_NODE 1025
#define F3     96
#define KCONV  36864
#define KLIN   4096
#define OUT_OC 0
#define OUT_OL 18874368
#define OUT_OB 19922944
#define AROWS  1056            // adjF rows padded (33*32)
#define APITCH 1152            // adjF col pitch padded (36*32)

// ---------------- scratch ----------------------------------------------------
__device__ float g_encG[32 * KCONV];     // conv enc weights gathered, [h][K]
__device__ float g_linG[32 * KLIN];      // lin  enc weights gathered, [h][K]
__device__ float g_feats[AROWS * F3];    // rows 1025.. stay 0 (static init)
__device__ float g_dinv[N_NODE];
__device__ float g_adjF[AROWS * APITCH]; // dinv[r]*(adj+I); pads stay 0
__device__ float g_t1[APITCH * F3];      // rows 1025.. stay 0
__device__ float g_h[AROWS * F3];        // PRE-relu accumulator (zeroed per launch)
__device__ float g_t2[APITCH * F3];      // rows 1025.. stay 0
__device__ float g_x[N_NODE * F3];       // accumulator (zeroed per launch)

__device__ __forceinline__ int conv_idx(int t) {
    int r = t / 9, s = t - r * 9;
    int a = r >> 6, b = r & 63;
    return a * 1152 + b * 9 + s;
}
__device__ __forceinline__ int lin_idx(int t) {
    return ((t >> 6) << 7) + (t & 63);
}

__device__ __forceinline__ void mma_tf32(float c[4], const unsigned a[4], const unsigned b[2]) {
    asm volatile("mma.sync.aligned.m16n8k8.row.col.f32.tf32.tf32.f32 "
                 "{%0,%1,%2,%3}, {%4,%5,%6,%7}, {%8,%9}, {%0,%1,%2,%3};"
                 : "+f"(c[0]), "+f"(c[1]), "+f"(c[2]), "+f"(c[3])
                 : "r"(a[0]), "r"(a[1]), "r"(a[2]), "r"(a[3]),
                   "r"(b[0]), "r"(b[1]));
}

__device__ __forceinline__ void cp16(unsigned dst_smem, const void* src) {
    asm volatile("cp.async.cg.shared.global [%0], [%1], 16;" :: "r"(dst_smem), "l"(src));
}

// ---------------- 1. gather BOTH encoder weight sets ------------------------
__global__ void k_prep_both(const float* __restrict__ Wc, const float* __restrict__ Wl) {
    int h = blockIdx.y;
    if (blockIdx.x < 144) {
        int t = blockIdx.x * 256 + threadIdx.x;
        g_encG[h * KCONV + t] = Wc[h * 147456 + conv_idx(t)];
    } else {
        int t = (blockIdx.x - 144) * 256 + threadIdx.x;
        g_linG[h * KLIN + t] = Wl[h * 16384 + lin_idx(t)];
    }
}

// ---------------- 2. init feats + dinv + adjF + zero h/x (fused) ------------
// adj row read ONCE into smem; sum and adjF write both served from it.
__global__ void k_init_dinv(const float* __restrict__ ceb, const float* __restrict__ leb,
                            const float* __restrict__ emb, const int* __restrict__ prims,
                            const int* __restrict__ adj) {
    __shared__ int arow[N_NODE];
    __shared__ int red[256];
    __shared__ float sdinv;
    int i = blockIdx.x;

    int e = i * 256 + threadIdx.x;
    if (e < N_NODE * F3) {
        int row = e / F3, c = e - row * F3;
        float v;
        if (row == 0) v = 1.0f;
        else {
            int ii = row - 1;
            if (c >= 64)      v = emb[prims[ii] * 32 + (c - 64)];
            else {
                int h = c & 31;
                if (ii < 512)      v = ceb[h];
                else if (ii < 768) v = leb[h];
                else               v = 0.0f;
            }
        }
        g_feats[e] = v;
    }

    for (int c = threadIdx.x; c < 96; c += 256) {
        g_h[i * 96 + c] = 0.0f;
        g_x[i * 96 + c] = 0.0f;
    }

    int s = 0;
    for (int j = threadIdx.x; j < N_NODE; j += 256) {
        int a = adj[i * N_NODE + j];
        arow[j] = a;
        s += a;
    }
    red[threadIdx.x] = s;
    __syncthreads();
    for (int off = 128; off > 0; off >>= 1) {
        if (threadIdx.x < off) red[threadIdx.x] += red[threadIdx.x + off];
        __syncthreads();
    }
    if (threadIdx.x == 0) {
        float d = rsqrtf((float)(red[0] + 1));
        g_dinv[i] = d;
        sdinv = d;
    }
    __syncthreads();
    float dv = sdinv;
    for (int l = threadIdx.x; l < N_NODE; l += 256) {
        float a = (float)arow[l] + (l == i ? 1.0f : 0.0f);
        g_adjF[i * APITCH + l] = dv * a;
    }
}

// ---------------- 4. encoder GEMM + bias encoder (merged) -------------------
__global__ __launch_bounds__(256) void k_enc_tf32(const float* __restrict__ Ac,
                                                  const float* __restrict__ Al,
                                                  const float* __restrict__ bw,
                                                  const float* __restrict__ Wb,
                                                  const float* __restrict__ bb) {
    if (blockIdx.y >= 76) {
        __shared__ float sW[32 * 65];
        __shared__ float sB[8 * 64];
        int bid = (blockIdx.y - 76) * 8 + blockIdx.x;
        int tid = threadIdx.x;
        for (int e = tid; e < 32 * 64; e += 256) {
            int hh = e >> 6, t = e & 63;
            sW[hh * 65 + t] = Wb[hh * 128 + t];
        }
        int ibase = bid * 8;
        for (int e = tid; e < 8 * 64; e += 256) sB[e] = bw[ibase * 64 + e];
        __syncthreads();
        int h = tid & 31, ii = tid >> 5;
        float acc = 0.0f;
#pragma unroll
        for (int t = 0; t < 64; t++) acc += sB[ii * 64 + t] * sW[h * 65 + t];
        acc += bb[h];
        int row = 769 + ibase + ii;
        g_feats[row * F3 + h] = acc;
        g_feats[row * F3 + 32 + h] = acc;
        return;
    }

    __shared__ unsigned As[3][64 * 40];
    __shared__ unsigned Bs[3][32 * 40];

    const float* A;
    const float* B;
    int K, featrow0, rowb, kbase;
    if (blockIdx.y < 72) {
        A = Ac; B = g_encG; K = KCONV; featrow0 = 1;
        rowb = blockIdx.x * 64;
        kbase = blockIdx.y * 512;
    } else {
        A = Al; B = g_linG; K = KLIN; featrow0 = 513;
        int id = (blockIdx.y - 72) * 8 + blockIdx.x;
        rowb = (id & 3) * 64;
        kbase = (id >> 2) * 512;
    }

    int tid = threadIdx.x;
    int warp = tid >> 5, lane = tid & 31;
    int g = lane >> 2, tg = lane & 3;
    int wm0 = (warp >> 1) * 16;
    int wn0 = (warp & 1) * 16;

    int mA0 = tid >> 3,            kqA0 = tid & 7;
    int mA1 = (tid + 256) >> 3,    kqA1 = (tid + 256) & 7;
    int mB  = tid >> 3,            kqB  = tid & 7;

    unsigned sA0[3], sA1[3], sB[3];
#pragma unroll
    for (int b = 0; b < 3; b++) {
        sA0[b] = (unsigned)__cvta_generic_to_shared(&As[b][mA0 * 40 + kqA0 * 4]);
        sA1[b] = (unsigned)__cvta_generic_to_shared(&As[b][mA1 * 40 + kqA1 * 4]);
        sB[b]  = (unsigned)__cvta_generic_to_shared(&Bs[b][mB * 40 + kqB * 4]);
    }

    const int NC = 16;
    auto issue = [&](int c) {
        int k0 = kbase + c * 32;
        int buf = c % 3;
        cp16(sA0[buf], &A[(rowb + mA0) * K + k0 + kqA0 * 4]);
        cp16(sA1[buf], &A[(rowb + mA1) * K + k0 + kqA1 * 4]);
        cp16(sB[buf],  &B[mB * K + k0 + kqB * 4]);
        asm volatile("cp.async.commit_group;");
    };

    issue(0);
    issue(1);

    float acc[2][4] = {};

    for (int c = 0; c < NC; c++) {
        if (c + 2 < NC) {
            issue(c + 2);
            asm volatile("cp.async.wait_group 2;");
        } else if (c + 1 < NC) {
            asm volatile("cp.async.wait_group 1;");
        } else {
            asm volatile("cp.async.wait_group 0;");
        }
        __syncthreads();

        const unsigned* Ab = As[c % 3];
        const unsigned* Bb = Bs[c % 3];
#pragma unroll
        for (int ks = 0; ks < 4; ks++) {
            int kk = ks * 8;
            unsigned a[4], b[2][2];
            a[0] = Ab[(wm0 + g) * 40 + kk + tg];
            a[1] = Ab[(wm0 + g + 8) * 40 + kk + tg];
            a[2] = Ab[(wm0 + g) * 40 + kk + tg + 4];
            a[3] = Ab[(wm0 + g + 8) * 40 + kk + tg + 4];
#pragma unroll
            for (int nt = 0; nt < 2; nt++) {
                b[nt][0] = Bb[(wn0 + nt * 8 + g) * 40 + kk + tg];
                b[nt][1] = Bb[(wn0 + nt * 8 + g) * 40 + kk + tg + 4];
            }
#pragma unroll
            for (int nt = 0; nt < 2; nt++) mma_tf32(acc[nt], a, b[nt]);
        }
        __syncthreads();
    }

#pragma unroll
    for (int nt = 0; nt < 2; nt++) {
        int h = wn0 + nt * 8 + 2 * tg;
        int r0 = featrow0 + rowb + wm0 + g;
        atomicAdd(&g_feats[r0 * F3 + h],          acc[nt][0]);
        atomicAdd(&g_feats[r0 * F3 + h + 1],      acc[nt][1]);
        atomicAdd(&g_feats[r0 * F3 + 32 + h],     acc[nt][0]);
        atomicAdd(&g_feats[r0 * F3 + 32 + h + 1], acc[nt][1]);
        int r1 = r0 + 8;
        atomicAdd(&g_feats[r1 * F3 + h],          acc[nt][2]);
        atomicAdd(&g_feats[r1 * F3 + h + 1],      acc[nt][3]);
        atomicAdd(&g_feats[r1 * F3 + 32 + h],     acc[nt][2]);
        atomicAdd(&g_feats[r1 * F3 + 32 + h + 1], acc[nt][3]);
    }
}

// ---------------- 6. GCN dense GEMM, tf32 MMA -------------------------------
// Grid 33, block 256. 32M x 96N x 96K, all staged in ONE cp.async batch.
// 8 warps = 2M x 4N (warp 16x24, 3 n-tiles). relu on A-load (sel=1),
// dinv scaling in epilogue. Smem: Is[32][104] + Ws[96][104] = 52 KB dynamic.
__global__ __launch_bounds__(256) void k_gcn_tf32(const float* __restrict__ W, int sel) {
    extern __shared__ unsigned gsm[];
    unsigned* Is = gsm;              // [32][104]
    unsigned* Ws = gsm + 32 * 104;   // [96][104]
    const float* __restrict__ in = sel ? g_h : g_feats;
    float* __restrict__ out = sel ? g_t2 : g_t1;

    int tid = threadIdx.x;
    int warp = tid >> 5, lane = tid & 31;
    int g = lane >> 2, tg = lane & 3;
    int wm0 = (warp >> 2) * 16;
    int wn0 = (warp & 3) * 24;
    int rowb = blockIdx.x * 32;

    // stage in: 32 rows x 96 = 768 f4 (3/thread); rows >=1025 read zero pad
#pragma unroll
    for (int i = 0; i < 3; i++) {
        int e = tid + i * 256;
        int m = e / 24, k4 = e - m * 24;
        cp16((unsigned)__cvta_generic_to_shared(&Is[m * 104 + k4 * 4]),
             &in[(rowb + m) * 96 + k4 * 4]);
    }
    // stage W: 96x96 = 2304 f4 (9/thread)
#pragma unroll
    for (int i = 0; i < 9; i++) {
        int e = tid + i * 256;
        int k = e / 24, j4 = e - k * 24;
        cp16((unsigned)__cvta_generic_to_shared(&Ws[k * 104 + j4 * 4]),
             &W[k * 96 + j4 * 4]);
    }
    asm volatile("cp.async.commit_group;");
    asm volatile("cp.async.wait_group 0;");
    __syncthreads();

    float acc[3][4] = {};
#pragma unroll
    for (int ks = 0; ks < 12; ks++) {
        int kk = ks * 8;
        unsigned a[4], b[3][2];
        a[0] = Is[(wm0 + g) * 104 + kk + tg];
        a[1] = Is[(wm0 + g + 8) * 104 + kk + tg];
        a[2] = Is[(wm0 + g) * 104 + kk + tg + 4];
        a[3] = Is[(wm0 + g + 8) * 104 + kk + tg + 4];
        if (sel) {
#pragma unroll
            for (int q = 0; q < 4; q++)
                a[q] = __float_as_uint(fmaxf(__uint_as_float(a[q]), 0.0f));
        }
#pragma unroll
        for (int ni = 0; ni < 3; ni++) {
            int n = wn0 + ni * 8 + g;
            b[ni][0] = Ws[(kk + tg) * 104 + n];
            b[ni][1] = Ws[(kk + tg + 4) * 104 + n];
        }
#pragma unroll
        for (int ni = 0; ni < 3; ni++) mma_tf32(acc[ni], a, b[ni]);
    }

    int r0 = rowb + wm0 + g;
    int r1 = r0 + 8;
    float d0 = (r0 < N_NODE) ? g_dinv[r0] : 0.0f;
    float d1 = (r1 < N_NODE) ? g_dinv[r1] : 0.0f;
#pragma unroll
    for (int ni = 0; ni < 3; ni++) {
        int col = wn0 + ni * 8 + 2 * tg;
        if (r0 < N_NODE) {
            float2 v = make_float2(acc[ni][0] * d0, acc[ni][1] * d0);
            *(float2*)&out[r0 * 96 + col] = v;
        }
        if (r1 < N_NODE) {
            float2 v = make_float2(acc[ni][2] * d1, acc[ni][3] * d1);
            *(float2*)&out[r1 * 96 + col] = v;
        }
    }
}

// ---------------- 7. SpMM as tf32 GEMM, split-K x4 --------------------------
__global__ __launch_bounds__(256) void k_spmm_tf32(int sel) {
    __shared__ unsigned As[2][32 * 40];
    __shared__ unsigned Ts[2][32 * 104];
    const float* __restrict__ ts = sel ? g_t2 : g_t1;
    float* __restrict__ out = sel ? g_x : g_h;

    int tid = threadIdx.x;
    int warp = tid >> 5, lane = tid & 31;
    int g = lane >> 2, tg = lane & 3;
    int wm0 = (warp >> 2) * 16;
    int wn0 = (warp & 3) * 24;
    int rowb = blockIdx.x * 32;
    int kbase = blockIdx.y * 288;

    int ar = tid >> 3, ak = tid & 7;
    int trr[3], tcc[3];
    unsigned adst[2], tdst[2][3];
#pragma unroll
    for (int b = 0; b < 2; b++)
        adst[b] = (unsigned)__cvta_generic_to_shared(&As[b][ar * 40 + ak * 4]);
#pragma unroll
    for (int i = 0; i < 3; i++) {
        int e = tid + i * 256;
        trr[i] = e / 24; tcc[i] = e - trr[i] * 24;
#pragma unroll
        for (int b = 0; b < 2; b++)
            tdst[b][i] = (unsigned)__cvta_generic_to_shared(&Ts[b][trr[i] * 104 + tcc[i] * 4]);
    }

    const int NC = 9;
    auto issue = [&](int c) {
        int buf = c & 1;
        int k0 = kbase + c * 32;
        cp16(adst[buf], &g_adjF[(rowb + ar) * APITCH + k0 + ak * 4]);
#pragma unroll
        for (int i = 0; i < 3; i++)
            cp16(tdst[buf][i], &ts[(k0 + trr[i]) * 96 + tcc[i] * 4]);
        asm volatile("cp.async.commit_group;");
    };

    issue(0);

    float acc[3][4] = {};
    for (int c = 0; c < NC; c++) {
        if (c + 1 < NC) {
            issue(c + 1);
            asm volatile("cp.async.wait_group 1;");
        } else {
            asm volatile("cp.async.wait_group 0;");
        }
        __syncthreads();

        const unsigned* Ab = As[c & 1];
        const unsigned* Tb = Ts[c & 1];
#pragma unroll
        for (int ks = 0; ks < 4; ks++) {
            int kk = ks * 8;
            unsigned a[4], b[3][2];
            a[0] = Ab[(wm0 + g) * 40 + kk + tg];
            a[1] = Ab[(wm0 + g + 8) * 40 + kk + tg];
            a[2] = Ab[(wm0 + g) * 40 + kk + tg + 4];
            a[3] = Ab[(wm0 + g + 8) * 40 + kk + tg + 4];
#pragma unroll
            for (int ni = 0; ni < 3; ni++) {
                int n = wn0 + ni * 8 + g;
                b[ni][0] = Tb[(kk + tg) * 104 + n];
                b[ni][1] = Tb[(kk + tg + 4) * 104 + n];
            }
#pragma unroll
            for (int ni = 0; ni < 3; ni++) mma_tf32(acc[ni], a, b[ni]);
        }
        __syncthreads();
    }

    int r0 = rowb + wm0 + g;
    int r1 = r0 + 8;
#pragma unroll
    for (int ni = 0; ni < 3; ni++) {
        int col = wn0 + ni * 8 + 2 * tg;
        if (r0 < N_NODE) {
            atomicAdd(&out[r0 * 96 + col],     acc[ni][0]);
            atomicAdd(&out[r0 * 96 + col + 1], acc[ni][1]);
        }
        if (r1 < N_NODE) {
            atomicAdd(&out[r1 * 96 + col],     acc[ni][2]);
            atomicAdd(&out[r1 * 96 + col + 1], acc[ni][3]);
        }
    }
}

// ---------------- 8. decoder GEMM: 128M x (jt*64)N, cp.async W --------------
__global__ __launch_bounds__(256) void k_dec_tf32(const float* __restrict__ Wd,
                                                  const float* __restrict__ bd,
                                                  float* __restrict__ out,
                                                  int Ntot, int xrow0, int mode,
                                                  long long outoff, int jt) {
    extern __shared__ unsigned smem[];
    unsigned* Xs = smem;                      // [128][104]
    unsigned* Ws0 = smem + 128 * 104;         // [2][64][104]

    int tid = threadIdx.x;
    int warp = tid >> 5, lane = tid & 31;
    int g = lane >> 2, tg = lane & 3;
    int wm0 = (warp >> 1) * 32;
    int wn0 = (warp & 1) * 32;
    int nbase = blockIdx.x * (jt * 64);
    int ibase = blockIdx.y * 128;

    int wrow[6], wk4[6];
    unsigned wdst[2][6];
#pragma unroll
    for (int i = 0; i < 6; i++) {
        int e = tid + i * 256;
        wrow[i] = e / 24;
        wk4[i] = e - wrow[i] * 24;
        wdst[0][i] = (unsigned)__cvta_generic_to_shared(&Ws0[wrow[i] * 104 + wk4[i] * 4]);
        wdst[1][i] = (unsigned)__cvta_generic_to_shared(&Ws0[64 * 104 + wrow[i] * 104 + wk4[i] * 4]);
    }
    auto issue_w = [&](int j) {
        int buf = j & 1;
#pragma unroll
        for (int i = 0; i < 6; i++) {
            int tglob = nbase + j * 64 + wrow[i];
            int id = (mode == 0) ? conv_idx(tglob) : lin_idx(tglob);
            cp16(wdst[buf][i], &Wd[id * 96 + wk4[i] * 4]);
        }
        asm volatile("cp.async.commit_group;");
    };

    issue_w(0);

#pragma unroll
    for (int i = 0; i < 12; i++) {
        int e = tid + i * 256;
        int m = e / 24, k4 = e - m * 24;
        float4 v = *(const float4*)&g_x[(xrow0 + ibase + m) * 96 + k4 * 4];
        *(float4*)&Xs[m * 104 + k4 * 4] = *(float4*)&v;
    }

    for (int j = 0; j < jt; j++) {
        if (j + 1 < jt) {
            issue_w(j + 1);
            asm volatile("cp.async.wait_group 1;");
        } else {
            asm volatile("cp.async.wait_group 0;");
        }
        __syncthreads();

        int tb = nbase + j * 64;
        float bx[4], by[4];
#pragma unroll
        for (int ni = 0; ni < 4; ni++) {
            int ncol = wn0 + ni * 8 + 2 * tg;
            int t0 = tb + ncol;
            int i0 = (mode == 0) ? conv_idx(t0) : lin_idx(t0);
            int i1 = (mode == 0) ? conv_idx(t0 + 1) : lin_idx(t0 + 1);
            bx[ni] = bd[i0];
            by[ni] = bd[i1];
        }

        const unsigned* Wb = Ws0 + (j & 1) * (64 * 104);
        float acc[2][4][4] = {};
#pragma unroll
        for (int ks = 0; ks < 12; ks++) {
            int k0 = ks * 8;
            unsigned a[2][4], b[4][2];
#pragma unroll
            for (int mi = 0; mi < 2; mi++) {
                int m = wm0 + mi * 16 + g;
                a[mi][0] = Xs[m * 104 + k0 + tg];
                a[mi][1] = Xs[(m + 8) * 104 + k0 + tg];
                a[mi][2] = Xs[m * 104 + k0 + tg + 4];
                a[mi][3] = Xs[(m + 8) * 104 + k0 + tg + 4];
            }
#pragma unroll
            for (int ni = 0; ni < 4; ni++) {
                int n = wn0 + ni * 8 + g;
                b[ni][0] = Wb[n * 104 + k0 + tg];
                b[ni][1] = Wb[n * 104 + k0 + tg + 4];
            }
#pragma unroll
            for (int mi = 0; mi < 2; mi++)
#pragma unroll
                for (int ni = 0; ni < 4; ni++)
                    mma_tf32(acc[mi][ni], a[mi], b[ni]);
        }

#pragma unroll
        for (int mi = 0; mi < 2; mi++) {
            int row0 = ibase + wm0 + mi * 16 + g;
#pragma unroll
            for (int ni = 0; ni < 4; ni++) {
                int col = tb + wn0 + ni * 8 + 2 * tg;
                float2 v0 = make_float2(acc[mi][ni][0] + bx[ni], acc[mi][ni][1] + by[ni]);
                float2 v1 = make_float2(acc[mi][ni][2] + bx[ni], acc[mi][ni][3] + by[ni]);
                *(float2*)&out[outoff + (long long)row0 * Ntot + col] = v0;
                *(float2*)&out[outoff + (long long)(row0 + 8) * Ntot + col] = v1;
            }
        }
        __syncthreads();
    }
}

// ---------------- 9. bias decoder (tiny) ------------------------------------
__global__ void k_dec_bias(const float* __restrict__ Wd, const float* __restrict__ bd,
                           float* __restrict__ out) {
    __shared__ float xr[96];
    int i = blockIdx.x;
    xr[threadIdx.x] = g_x[(769 + i) * 96 + threadIdx.x];
    __syncthreads();
    int t = threadIdx.x;
    if (t < 64) {
        float acc = 0.0f;
#pragma unroll 8
        for (int k = 0; k < 96; k++) acc += xr[k] * Wd[t * 96 + k];
        out[OUT_OB + i * 64 + t] = acc + bd[t];
    }
}

// ---------------- launch -----------------------------------------------------
extern "C" void kernel_launch(void* const* d_in, const int* in_sizes, int n_in,
                              void* d_out, int out_size) {
    const float* conv_w     = (const float*)d_in[0];
    const float* lin_w      = (const float*)d_in[1];
    const float* bias_w     = (const float*)d_in[2];
    const float* conv_enc_w = (const float*)d_in[3];
    const float* conv_enc_b = (const float*)d_in[4];
    const float* lin_enc_w  = (const float*)d_in[5];
    const float* lin_enc_b  = (const float*)d_in[6];
    const float* bias_enc_w = (const float*)d_in[7];
    const float* bias_enc_b = (const float*)d_in[8];
    const float* gcn_w1     = (const float*)d_in[9];
    const float* gcn_w2     = (const float*)d_in[10];
    const float* conv_dec_w = (const float*)d_in[11];
    const float* conv_dec_b = (const float*)d_in[12];
    const float* lin_dec_w  = (const float*)d_in[13];
    const float* lin_dec_b  = (const float*)d_in[14];
    const float* bias_dec_w = (const float*)d_in[15];
    const float* bias_dec_b = (const float*)d_in[16];
    const float* embed_tab  = (const float*)d_in[17];
    const int*   adj        = (const int*)d_in[18];
    const int*   node_prims = (const int*)d_in[19];
    float* out = (float*)d_out;

    (void)in_sizes; (void)n_in; (void)out_size;

    const int DEC_SMEM = (128 * 104 + 2 * 64 * 104) * 4;   // 106496 B
    const int GCN_SMEM = (32 * 104 + 96 * 104) * 4;        // 53248 B
    static int smem_set = 0;
    if (!smem_set) {
        cudaFuncSetAttribute(k_dec_tf32, cudaFuncAttributeMaxDynamicSharedMemorySize, DEC_SMEM);
        cudaFuncSetAttribute(k_gcn_tf32, cudaFuncAttributeMaxDynamicSharedMemorySize, GCN_SMEM);
        smem_set = 1;
    }

    k_prep_both<<<dim3(160, 32), 256>>>(conv_enc_w, lin_enc_w);                      // 0
    k_init_dinv<<<N_NODE, 256>>>(conv_enc_b, lin_enc_b, embed_tab, node_prims, adj); // 1
    k_enc_tf32<<<dim3(8, 80), 256>>>(conv_w, lin_w, bias_w, bias_enc_w, bias_enc_b); // 2
    k_gcn_tf32<<<33, 256, GCN_SMEM>>>(gcn_w1, 0);                                    // 3 <- profiled
    k_spmm_tf32<<<dim3(33, 4), 256>>>(0);
    k_gcn_tf32<<<33, 256, GCN_SMEM>>>(gcn_w2, 1);
    k_spmm_tf32<<<dim3(33, 4), 256>>>(1);

    k_dec_tf32<<<dim3(72, 4), 256, DEC_SMEM>>>(conv_dec_w, conv_dec_b, out, 36864, 1, 0, (long long)OUT_OC, 8);
    k_dec_tf32<<<dim3(64, 2), 256, DEC_SMEM>>>(lin_dec_w, lin_dec_b, out, 4096, 513, 1, (long long)OUT_OL, 1);
    k_dec_bias<<<256, 96>>>(bias_dec_w, bias_dec_b, out);
}